// round 14
// baseline (speedup 1.0000x reference)
#include <cuda_runtime.h>

#define NNZ     4194304
#define DENSE   16
#define DIMLOG  13
#define DIMSZ   8192
#define WORDS   2097152u           // 2^26 cells / 32
#define SCAN_BLOCKS 2048
#define SCAN_WPT 4
#define STAGE_CAP 4096
#define GATHER_BLOCKS (NNZ / 128)  // 16 slots/warp, 8 warps/block
#define RESET_BLOCKS 256

#define ENT_DUP  0xFFFFFFFFu       // slot fed by atomics in phaseA
#define ENT_PAD  0xFFFFFFFEu

// Occupancy bitmap (8MB). Zero at entry; reset inline by scan.
__device__ __align__(16) unsigned g_occ[WORDS];
// Dup bitmap (8MB). Zero at entry; reset by gather tail blocks.
__device__ __align__(16) unsigned g_dupb[WORDS];
// Scan-written metadata: {bm, exclusive slot offset of bit0} (16MB, L2-res).
__device__ __align__(16) uint2 g_meta2[WORDS];
// slot -> contributing entry id (16.8MB, L2-resident during phaseA/gather).
__device__ unsigned g_ent[NNZ];
__device__ unsigned g_desc[SCAN_BLOCKS];
__device__ unsigned g_ticket;
__device__ unsigned g_total;

// ---------------------------------------------------------------------------
__device__ __forceinline__ unsigned block_exscan(unsigned v, unsigned& blocktotal) {
    __shared__ unsigned warp_sums[8];
    __shared__ unsigned warp_off[8];
    unsigned lane = threadIdx.x & 31u, wid = threadIdx.x >> 5;
    unsigned x = v;
#pragma unroll
    for (int d = 1; d < 32; d <<= 1) {
        unsigned y = __shfl_up_sync(0xffffffffu, x, d);
        if ((int)lane >= d) x += y;
    }
    if (lane == 31) warp_sums[wid] = x;
    __syncthreads();
    if (threadIdx.x < 8) {
        unsigned s = warp_sums[threadIdx.x];
        unsigned inc = s;
#pragma unroll
        for (int d = 1; d < 8; d <<= 1) {
            unsigned y = __shfl_up_sync(0xffu, inc, d);
            if ((int)threadIdx.x >= d) inc += y;
        }
        warp_off[threadIdx.x] = inc - s;
    }
    __syncthreads();
    blocktotal = warp_off[7] + warp_sums[7];
    return warp_off[wid] + (x - v);
}

// ---------------------------------------------------------------------------
// Load 8 flat cell ids for entries 8i..8i+7.
__device__ __forceinline__ void load_flat8(const int* __restrict__ idx,
                                           unsigned i, unsigned* f) {
    int4 r0 = __ldg((const int4*)idx + 2 * i);
    int4 r1 = __ldg((const int4*)idx + 2 * i + 1);
    int4 c0 = __ldg((const int4*)(idx + NNZ) + 2 * i);
    int4 c1 = __ldg((const int4*)(idx + NNZ) + 2 * i + 1);
    f[0] = ((unsigned)r0.x << DIMLOG) | (unsigned)c0.x;
    f[1] = ((unsigned)r0.y << DIMLOG) | (unsigned)c0.y;
    f[2] = ((unsigned)r0.z << DIMLOG) | (unsigned)c0.z;
    f[3] = ((unsigned)r0.w << DIMLOG) | (unsigned)c0.w;
    f[4] = ((unsigned)r1.x << DIMLOG) | (unsigned)c1.x;
    f[5] = ((unsigned)r1.y << DIMLOG) | (unsigned)c1.y;
    f[6] = ((unsigned)r1.z << DIMLOG) | (unsigned)c1.z;
    f[7] = ((unsigned)r1.w << DIMLOG) | (unsigned)c1.w;
}

// B: mark occupancy + dup bits. 8 entries/thread for deep atomic MLP.
__global__ void k_mark(const int* __restrict__ idx) {
    unsigned i = blockIdx.x * 256u + threadIdx.x;
    unsigned f[8];
    load_flat8(idx, i, f);
    unsigned old[8];
#pragma unroll
    for (int j = 0; j < 8; j++)
        old[j] = atomicOr(&g_occ[f[j] >> 5], 1u << (f[j] & 31u));
#pragma unroll
    for (int j = 0; j < 8; j++)
        if ((old[j] >> (f[j] & 31u)) & 1u)
            atomicOr(&g_dupb[f[j] >> 5], 1u << (f[j] & 31u));
}

// S: single-pass scan (decoupled lookback) + meta2 writes + occ reset +
//    smem-staged compact of unique indices + dup-row pre-zero + n_unique.
__global__ void k_scan_compact(float* __restrict__ out) {
    __shared__ unsigned sh_lbid, sh_prefix;
    __shared__ float s0[STAGE_CAP];
    __shared__ float s1[STAGE_CAP];
    unsigned tid = threadIdx.x;
    if (tid == 0) sh_lbid = atomicAdd(&g_ticket, 1u);
    __syncthreads();
    unsigned lbid = sh_lbid;
    unsigned base = lbid * (256u * SCAN_WPT) + tid * SCAN_WPT;

    uint4 ow = *((const uint4*)(g_occ + base));        // 4 occ words
    uint4 dw = *((const uint4*)(g_dupb + base));       // 4 dup words
    unsigned bm[SCAN_WPT] = {ow.x, ow.y, ow.z, ow.w};
    unsigned du[SCAN_WPT] = {dw.x, dw.y, dw.z, dw.w};
    unsigned s = __popc(bm[0]) + __popc(bm[1]) + __popc(bm[2]) + __popc(bm[3]);
    unsigned tot;
    unsigned ex = block_exscan(s, tot);

    if (tid < 32) {
        if (tid == 0) atomicExch(&g_desc[lbid], (tot << 2) | (lbid == 0 ? 2u : 1u));
        unsigned prefix = 0;
        if (lbid > 0) {
            int look = (int)lbid - 1;
            unsigned running = 0;
            while (true) {
                int j = look - 31 + (int)tid;
                unsigned d;
                if (j < 0) d = 2u;
                else {
                    do { d = *((volatile unsigned*)(g_desc + j)); } while ((d & 3u) == 0u);
                }
                unsigned ball = __ballot_sync(0xffffffffu, (d & 3u) == 2u);
                if (ball) {
                    int hi = 31 - __clz(ball);
                    unsigned contrib = ((int)tid >= hi) ? (d >> 2) : 0u;
                    running += __reduce_add_sync(0xffffffffu, contrib);
                    break;
                } else {
                    running += __reduce_add_sync(0xffffffffu, d >> 2);
                    look -= 32;
                }
            }
            prefix = running;
            if (tid == 0) atomicExch(&g_desc[lbid], ((prefix + tot) << 2) | 2u);
        }
        if (tid == 0) sh_prefix = prefix;
    }
    __syncthreads();

    unsigned prefix = sh_prefix;
    unsigned off = prefix + ex;
    if (lbid == SCAN_BLOCKS - 1 && tid == 0) {
        unsigned nu = prefix + tot;
        g_total = nu;
        out[(size_t)2 * NNZ + (size_t)NNZ * DENSE] = (float)nu;
    }

    // meta2: pack 4 {bm,off} pairs into two uint4 stores; reset occ words.
    {
        unsigned o = off;
        unsigned offs[SCAN_WPT];
#pragma unroll
        for (int j = 0; j < SCAN_WPT; j++) { offs[j] = o; o += __popc(bm[j]); }
        uint4* dst = (uint4*)(g_meta2 + base);
        uint4 a = {bm[0], offs[0], bm[1], offs[1]};
        uint4 b = {bm[2], offs[2], bm[3], offs[3]};
        dst[0] = a; dst[1] = b;
        uint4 z = {0u, 0u, 0u, 0u};
        __stcs((uint4*)(g_occ + base), z);             // occ reset for next run
    }

    float* out0 = out;
    float* out1 = out + NNZ;
    float* vout = out + (size_t)2 * NNZ;
    bool staged = (tot <= STAGE_CAP);

#pragma unroll
    for (int j = 0; j < SCAN_WPT; j++) {
        unsigned w = base + j;
        unsigned o = off;
        unsigned v = bm[j];
        unsigned dup = du[j];
        while (v) {
            unsigned b = (unsigned)__ffs(v) - 1u;
            v &= v - 1u;
            unsigned cell = (w << 5) | b;
            float rf = (float)(cell >> DIMLOG);
            float cf = (float)(cell & (DIMSZ - 1));
            if (staged) {
                unsigned lo = o - prefix;
                s0[lo] = rf; s1[lo] = cf;
            } else {
                __stcs(out0 + o, rf);
                __stcs(out1 + o, cf);
            }
            if ((dup >> b) & 1u) {               // pre-zero rows that accumulate
                float4* p = (float4*)(vout + (size_t)o * DENSE);
                float4 z = {0.f, 0.f, 0.f, 0.f};
                __stcs(p + 0, z); __stcs(p + 1, z); __stcs(p + 2, z); __stcs(p + 3, z);
            }
            o++;
        }
        off = o;
    }

    if (staged) {
        __syncthreads();
        for (unsigned i = tid; i < tot; i += 256u) {
            __stcs(out0 + prefix + i, s0[i]);
            __stcs(out1 + prefix + i, s1[i]);
        }
    }
}

// A: entry -> slot map, 8 entries/thread (16 front-batched L2-resident random
// loads). Non-dup entries claim their slot with a plain 4B store. Dup-cell
// contributors (~3%) mark ENT_DUP and atomicAdd onto the pre-zeroed row.
__global__ void k_phaseA(const int* __restrict__ idx,
                         const float* __restrict__ vals,
                         float* __restrict__ out) {
    float* vout = out + (size_t)2 * NNZ;
    unsigned i = blockIdx.x * 256u + threadIdx.x;      // entries 8i..8i+7
    unsigned f[8];
    load_flat8(idx, i, f);
    uint2 mt[8];
    unsigned dwd[8];
#pragma unroll
    for (int j = 0; j < 8; j++) mt[j] = __ldg(&g_meta2[f[j] >> 5]);
#pragma unroll
    for (int j = 0; j < 8; j++) dwd[j] = __ldg(&g_dupb[f[j] >> 5]);
#pragma unroll
    for (int j = 0; j < 8; j++) {
        unsigned b = f[j] & 31u;
        unsigned slot = mt[j].y + __popc(mt[j].x & ((1u << b) - 1u));
        unsigned e = 8u * i + (unsigned)j;
        if ((dwd[j] >> b) & 1u) {                      // dup cell
            g_ent[slot] = ENT_DUP;                     // benign multi-writer race
            const float4* src = (const float4*)vals + (size_t)e * 4;
            float* dst = vout + (size_t)slot * DENSE;
#pragma unroll
            for (int q = 0; q < 4; q++) {
                float4 v = __ldg(src + q);
                atomicAdd(dst + q * 4 + 0, v.x);
                atomicAdd(dst + q * 4 + 1, v.y);
                atomicAdd(dst + q * 4 + 2, v.z);
                atomicAdd(dst + q * 4 + 3, v.w);
            }
        } else {
            g_ent[slot] = e;                           // unique writer
        }
    }
}

// G: gather. Warp handles 16 consecutive slots: sequential g_ent reads,
// RANDOM value-row READS, SEQUENTIAL output writes. Dup slots skipped;
// tail slots filled inline. Extra blocks reset dup bitmap + desc + ticket.
__global__ void k_gather(const float* __restrict__ vals,
                         float* __restrict__ out) {
    float* vout = out + (size_t)2 * NNZ;

    if (blockIdx.x >= GATHER_BLOCKS) {
        unsigned tb = blockIdx.x - GATHER_BLOCKS;
        unsigned t0 = tb * 256u + threadIdx.x;
        uint4 z = {0u, 0u, 0u, 0u};
        for (unsigned i = t0; i < WORDS / 4; i += RESET_BLOCKS * 256u)
            __stcs(((uint4*)g_dupb) + i, z);
        if (tb == 0) {
            if (threadIdx.x < SCAN_BLOCKS / 4) ((uint4*)g_desc)[threadIdx.x] = z;
            if (threadIdx.x == 0) g_ticket = 0u;
        }
        return;
    }

    unsigned t = blockIdx.x * 256u + threadIdx.x;
    unsigned lane = threadIdx.x & 31u;
    unsigned warpSlot0 = (t >> 5) * 16u;
    unsigned nu = g_total;

    unsigned e = 0;
    if (lane < 16) {
        unsigned slot = warpSlot0 + lane;
        if (slot < nu) {
            e = __ldg(g_ent + slot);                 // sequential
        } else {
            e = ENT_PAD;                             // tail slot
            __stcs(out + slot, 8192.0f);             // index padding
            __stcs(out + NNZ + slot, 0.0f);
        }
    }
    unsigned eR = __shfl_sync(0xffffffffu, e, lane >> 1);
    unsigned slot = warpSlot0 + (lane >> 1);
    unsigned sub = (lane & 1u) * 2u;

    if (eR == ENT_DUP) return;                       // row done by phaseA
    float4* dst = (float4*)(vout + (size_t)slot * DENSE + sub * 4);
    if (eR == ENT_PAD) {
        float4 z = {0.f, 0.f, 0.f, 0.f};
        __stcs(dst + 0, z);
        __stcs(dst + 1, z);
    } else {
        const float4* src = (const float4*)vals + (size_t)eR * 4 + sub;
        float4 v0 = __ldcs(src + 0);                 // random 64B read
        float4 v1 = __ldcs(src + 1);
        __stcs(dst + 0, v0);                         // sequential write
        __stcs(dst + 1, v1);
    }
}

// ---------------------------------------------------------------------------
extern "C" void kernel_launch(void* const* d_in, const int* in_sizes, int n_in,
                              void* d_out, int out_size) {
    (void)in_sizes; (void)n_in; (void)out_size;
    const int*   idx  = (const int*)d_in[0];
    const float* vals = (const float*)d_in[1];
    float* out = (float*)d_out;

    k_mark        <<<NNZ / 8 / 256, 256>>>(idx);
    k_scan_compact<<<SCAN_BLOCKS,   256>>>(out);
    k_phaseA      <<<NNZ / 8 / 256, 256>>>(idx, vals, out);
    k_gather      <<<GATHER_BLOCKS + RESET_BLOCKS, 256>>>(vals, out);
}

// round 15
// speedup vs baseline: 1.1414x; 1.1414x over previous
#include <cuda_runtime.h>

#define NNZ     4194304
#define DENSE   16
#define DIMLOG  13
#define DIMSZ   8192
#define WORDS   2097152u           // 2^26 cells / 32
#define SCAN_BLOCKS 2048
#define SCAN_WPT 4
#define STAGE_CAP 4096
#define MAIN_BLOCKS (NNZ / 128)    // 16 rows/warp, 8 warps/block
#define TAIL_BLOCKS 256

// Mark-phase bits: x=occupancy, y=dup (16MB). Zero at entry; reset by scan.
__device__ __align__(16) uint2 g_bits[WORDS];
// Scan-written metadata: x=bm, y=dup, z=excl slot offset of bit0 (32MB).
__device__ __align__(16) uint4 g_meta[WORDS];
__device__ unsigned g_desc[SCAN_BLOCKS];
__device__ unsigned g_ticket;
__device__ unsigned g_total;

// ---------------------------------------------------------------------------
__device__ __forceinline__ unsigned block_exscan(unsigned v, unsigned& blocktotal) {
    __shared__ unsigned warp_sums[8];
    __shared__ unsigned warp_off[8];
    unsigned lane = threadIdx.x & 31u, wid = threadIdx.x >> 5;
    unsigned x = v;
#pragma unroll
    for (int d = 1; d < 32; d <<= 1) {
        unsigned y = __shfl_up_sync(0xffffffffu, x, d);
        if ((int)lane >= d) x += y;
    }
    if (lane == 31) warp_sums[wid] = x;
    __syncthreads();
    if (threadIdx.x < 8) {
        unsigned s = warp_sums[threadIdx.x];
        unsigned inc = s;
#pragma unroll
        for (int d = 1; d < 8; d <<= 1) {
            unsigned y = __shfl_up_sync(0xffu, inc, d);
            if ((int)threadIdx.x >= d) inc += y;
        }
        warp_off[threadIdx.x] = inc - s;
    }
    __syncthreads();
    blocktotal = warp_off[7] + warp_sums[7];
    return warp_off[wid] + (x - v);
}

// ---------------------------------------------------------------------------
// B: mark occupancy + dup bits. 8 entries/thread for deep atomic MLP.
__global__ void k_mark(const int* __restrict__ idx) {
    unsigned i = blockIdx.x * 256u + threadIdx.x;
    int4 r0 = __ldg((const int4*)idx + 2 * i);
    int4 r1 = __ldg((const int4*)idx + 2 * i + 1);
    int4 c0 = __ldg((const int4*)(idx + NNZ) + 2 * i);
    int4 c1 = __ldg((const int4*)(idx + NNZ) + 2 * i + 1);
    unsigned f[8] = {
        ((unsigned)r0.x << DIMLOG) | (unsigned)c0.x,
        ((unsigned)r0.y << DIMLOG) | (unsigned)c0.y,
        ((unsigned)r0.z << DIMLOG) | (unsigned)c0.z,
        ((unsigned)r0.w << DIMLOG) | (unsigned)c0.w,
        ((unsigned)r1.x << DIMLOG) | (unsigned)c1.x,
        ((unsigned)r1.y << DIMLOG) | (unsigned)c1.y,
        ((unsigned)r1.z << DIMLOG) | (unsigned)c1.z,
        ((unsigned)r1.w << DIMLOG) | (unsigned)c1.w };
    unsigned old[8];
#pragma unroll
    for (int j = 0; j < 8; j++)
        old[j] = atomicOr(&g_bits[f[j] >> 5].x, 1u << (f[j] & 31u));
#pragma unroll
    for (int j = 0; j < 8; j++)
        if ((old[j] >> (f[j] & 31u)) & 1u)
            atomicOr(&g_bits[f[j] >> 5].y, 1u << (f[j] & 31u));
}

// S: single-pass scan (decoupled lookback) + full-line meta writes + inline
//    g_bits reset + smem-staged compact of unique indices + dup-row pre-zero
//    + n_unique. Last block resets the ticket (all increments are done).
__global__ void k_scan_compact(float* __restrict__ out) {
    __shared__ unsigned sh_lbid, sh_prefix;
    __shared__ float s0[STAGE_CAP];
    __shared__ float s1[STAGE_CAP];
    unsigned tid = threadIdx.x;
    if (tid == 0) sh_lbid = atomicAdd(&g_ticket, 1u);
    __syncthreads();
    unsigned lbid = sh_lbid;
    unsigned base = lbid * (256u * SCAN_WPT) + tid * SCAN_WPT;

    uint2 bd[SCAN_WPT];
    {   // two LDG.128s cover 4 words of {occ,dup}
        uint4 a = *((const uint4*)(g_bits + base));
        uint4 b = *((const uint4*)(g_bits + base + 2));
        bd[0].x = a.x; bd[0].y = a.y; bd[1].x = a.z; bd[1].y = a.w;
        bd[2].x = b.x; bd[2].y = b.y; bd[3].x = b.z; bd[3].y = b.w;
    }
    // Reset our exclusively-owned words for the next run.
    {
        uint4 z = {0u, 0u, 0u, 0u};
        __stcs((uint4*)(g_bits + base), z);
        __stcs((uint4*)(g_bits + base + 2), z);
    }
    unsigned s = 0;
#pragma unroll
    for (int j = 0; j < SCAN_WPT; j++) s += __popc(bd[j].x);
    unsigned tot;
    unsigned ex = block_exscan(s, tot);

    if (tid < 32) {
        if (tid == 0) atomicExch(&g_desc[lbid], (tot << 2) | (lbid == 0 ? 2u : 1u));
        unsigned prefix = 0;
        if (lbid > 0) {
            int look = (int)lbid - 1;
            unsigned running = 0;
            while (true) {
                int j = look - 31 + (int)tid;
                unsigned d;
                if (j < 0) d = 2u;
                else {
                    do { d = *((volatile unsigned*)(g_desc + j)); } while ((d & 3u) == 0u);
                }
                unsigned ball = __ballot_sync(0xffffffffu, (d & 3u) == 2u);
                if (ball) {
                    int hi = 31 - __clz(ball);
                    unsigned contrib = ((int)tid >= hi) ? (d >> 2) : 0u;
                    running += __reduce_add_sync(0xffffffffu, contrib);
                    break;
                } else {
                    running += __reduce_add_sync(0xffffffffu, d >> 2);
                    look -= 32;
                }
            }
            prefix = running;
            if (tid == 0) atomicExch(&g_desc[lbid], ((prefix + tot) << 2) | 2u);
        }
        if (tid == 0) sh_prefix = prefix;
    }
    __syncthreads();

    unsigned prefix = sh_prefix;
    unsigned off = prefix + ex;
    if (lbid == SCAN_BLOCKS - 1 && tid == 0) {
        unsigned nu = prefix + tot;
        g_total = nu;
        out[(size_t)2 * NNZ + (size_t)NNZ * DENSE] = (float)nu;
        g_ticket = 0u;   // all 2048 increments observed; safe to reset
    }

    float* out0 = out;
    float* out1 = out + NNZ;
    float* vout = out + (size_t)2 * NNZ;
    bool staged = (tot <= STAGE_CAP);

#pragma unroll
    for (int j = 0; j < SCAN_WPT; j++) {
        unsigned w = base + j;
        unsigned bm = bd[j].x, dup = bd[j].y;
        uint4 m4; m4.x = bm; m4.y = dup; m4.z = off; m4.w = 0u;
        g_meta[w] = m4;                          // full-line STG.128
        unsigned o = off;
        unsigned v = bm;
        while (v) {
            unsigned b = (unsigned)__ffs(v) - 1u;
            v &= v - 1u;
            unsigned cell = (w << 5) | b;
            float rf = (float)(cell >> DIMLOG);
            float cf = (float)(cell & (DIMSZ - 1));
            if (staged) {
                unsigned lo = o - prefix;
                s0[lo] = rf; s1[lo] = cf;
            } else {
                __stcs(out0 + o, rf);
                __stcs(out1 + o, cf);
            }
            if ((dup >> b) & 1u) {               // pre-zero rows that accumulate
                float4* p = (float4*)(vout + (size_t)o * DENSE);
                float4 z = {0.f, 0.f, 0.f, 0.f};
                __stcs(p + 0, z); __stcs(p + 1, z); __stcs(p + 2, z); __stcs(p + 3, z);
            }
            o++;
        }
        off = o;
    }

    if (staged) {
        __syncthreads();
        for (unsigned i = tid; i < tot; i += 256u) {
            __stcs(out0 + prefix + i, s0[i]);
            __stcs(out1 + prefix + i, s1[i]);
        }
    }
}

// ---------------------------------------------------------------------------
// One 8-row value batch: 4 lanes per row, one float4 each -> every STG.128
// covers a full 64B row; 8 distinct lines per instruction (1 wavefront/row,
// half of the 2-lanes/row scheme).
__device__ __forceinline__ void move_rows4(unsigned packed, unsigned rowIdx,
                                           unsigned sub,
                                           const float* __restrict__ vals,
                                           float* __restrict__ vout) {
    unsigned slot = packed >> 1, dup = packed & 1u;
    float4 v = __ldcs((const float4*)vals + (size_t)rowIdx * 4 + sub);
    float* dst = vout + (size_t)slot * DENSE + sub * 4;
    if (dup) {
        atomicAdd(dst + 0, v.x); atomicAdd(dst + 1, v.y);
        atomicAdd(dst + 2, v.z); atomicAdd(dst + 3, v.w);
    } else {
        __stcs((float4*)dst, v);
    }
}

// E: scatter. 16 rows/warp: lanes 0..15 resolve (slot,dup) -> 16 random meta
// sectors in flight; then two 8-row batches move values at 4 lanes/row
// (full-line stores, 2 independent loads/stores per thread).
// Tail blocks: padding fill + desc reset.
__global__ void k_scatter(const int* __restrict__ idx,
                          const float* __restrict__ vals,
                          float* __restrict__ out) {
    float* vout = out + (size_t)2 * NNZ;

    if (blockIdx.x >= MAIN_BLOCKS) {
        unsigned tb = blockIdx.x - MAIN_BLOCKS;
        unsigned t0 = tb * 256u + threadIdx.x;
        unsigned nu = g_total;
        float4 z4 = {0.f, 0.f, 0.f, 0.f};
        for (unsigned slot = nu + t0; slot < NNZ; slot += TAIL_BLOCKS * 256u) {
            __stcs(out + slot, 8192.0f);
            __stcs(out + NNZ + slot, 0.0f);
            float4* v = (float4*)(vout + (size_t)slot * DENSE);
            __stcs(v + 0, z4); __stcs(v + 1, z4); __stcs(v + 2, z4); __stcs(v + 3, z4);
        }
        if (tb == 0) {
            uint4 z = {0u, 0u, 0u, 0u};
            if (threadIdx.x < SCAN_BLOCKS / 4) ((uint4*)g_desc)[threadIdx.x] = z;
        }
        return;
    }

    unsigned t = blockIdx.x * 256u + threadIdx.x;
    unsigned lane = threadIdx.x & 31u;
    unsigned warpRow0 = (t >> 5) * 16u;

    unsigned packed = 0;
    if (lane < 16) {
        unsigned r = warpRow0 + lane;
        unsigned flat = ((unsigned)__ldg(idx + r) << DIMLOG) | (unsigned)__ldg(idx + NNZ + r);
        unsigned w = flat >> 5, b = flat & 31u;
        uint4 mt = __ldg(&g_meta[w]);          // 1 sector: bm, dup, off
        unsigned slot = mt.z + __popc(mt.x & ((1u << b) - 1u));
        packed = (slot << 1) | ((mt.y >> b) & 1u);
    }

    // Batch A: rows warpRow0+0..7 ; Batch B: rows warpRow0+8..15.
    unsigned rA = lane >> 2;                       // 0..7
    unsigned pA = __shfl_sync(0xffffffffu, packed, rA);
    unsigned pB = __shfl_sync(0xffffffffu, packed, 8u + rA);
    unsigned sub = lane & 3u;                      // quarter within the row
    unsigned iA = warpRow0 + rA;
    unsigned iB = iA + 8u;

    move_rows4(pA, iA, sub, vals, vout);
    move_rows4(pB, iB, sub, vals, vout);
}

// ---------------------------------------------------------------------------
extern "C" void kernel_launch(void* const* d_in, const int* in_sizes, int n_in,
                              void* d_out, int out_size) {
    (void)in_sizes; (void)n_in; (void)out_size;
    const int*   idx  = (const int*)d_in[0];
    const float* vals = (const float*)d_in[1];
    float* out = (float*)d_out;

    k_mark        <<<NNZ / 8 / 256, 256>>>(idx);
    k_scan_compact<<<SCAN_BLOCKS,   256>>>(out);
    k_scatter     <<<MAIN_BLOCKS + TAIL_BLOCKS, 256>>>(idx, vals, out);
}

// round 17
// speedup vs baseline: 1.2256x; 1.0738x over previous
#include <cuda_runtime.h>

#define NNZ     4194304
#define DENSE   16
#define DIMLOG  13
#define DIMSZ   8192
#define WORDS   2097152u           // 2^26 cells / 32
#define SCAN_BLOCKS 2048
#define SCAN_WPT 4
#define STAGE_CAP 4096
#define MAIN_BLOCKS (NNZ / 128)    // 16 rows/warp, 8 warps/block
#define TAIL_BLOCKS 256

// Compact mark-phase bits: x=occupancy, y=dup. 16MB, zeroed each run.
__device__ __align__(16) uint2 g_bits[WORDS];
// Scatter-phase metadata written by scan with full-line stores:
// x=occupancy bits, y=dup bits, z=exclusive slot offset of bit 0. Not zeroed.
__device__ __align__(16) uint4 g_meta[WORDS];
__device__ unsigned g_desc[SCAN_BLOCKS];
__device__ unsigned g_ticket;
__device__ unsigned g_total;

// ---------------------------------------------------------------------------
__device__ __forceinline__ unsigned block_exscan(unsigned v, unsigned& blocktotal) {
    __shared__ unsigned warp_sums[8];
    __shared__ unsigned warp_off[8];
    unsigned lane = threadIdx.x & 31u, wid = threadIdx.x >> 5;
    unsigned x = v;
#pragma unroll
    for (int d = 1; d < 32; d <<= 1) {
        unsigned y = __shfl_up_sync(0xffffffffu, x, d);
        if ((int)lane >= d) x += y;
    }
    if (lane == 31) warp_sums[wid] = x;
    __syncthreads();
    if (threadIdx.x < 8) {
        unsigned s = warp_sums[threadIdx.x];
        unsigned inc = s;
#pragma unroll
        for (int d = 1; d < 8; d <<= 1) {
            unsigned y = __shfl_up_sync(0xffu, inc, d);
            if ((int)threadIdx.x >= d) inc += y;
        }
        warp_off[threadIdx.x] = inc - s;
    }
    __syncthreads();
    blocktotal = warp_off[7] + warp_sums[7];
    return warp_off[wid] + (x - v);
}

// ---------------------------------------------------------------------------
// Z: zero mark bits (16MB) + lookback descriptors + ticket
__global__ void k_zero() {
    unsigned i = blockIdx.x * 256u + threadIdx.x;
    uint4 z = {0u, 0u, 0u, 0u};
    if (i < WORDS / 2)                        ((uint4*)g_bits)[i] = z;
    else if (i < WORDS/2 + SCAN_BLOCKS/4)     ((uint4*)g_desc)[i - WORDS/2] = z;
    else if (i == WORDS/2 + SCAN_BLOCKS/4)    g_ticket = 0u;
}

// B: mark occupancy + duplicate bits. 4 entries/thread, int4 loads.
__global__ void k_mark(const int* __restrict__ idx) {
    unsigned i = blockIdx.x * 256u + threadIdx.x;
    int4 r = __ldcs((const int4*)idx + i);
    int4 c = __ldcs((const int4*)(idx + NNZ) + i);
    unsigned f[4] = {
        ((unsigned)r.x << DIMLOG) | (unsigned)c.x,
        ((unsigned)r.y << DIMLOG) | (unsigned)c.y,
        ((unsigned)r.z << DIMLOG) | (unsigned)c.z,
        ((unsigned)r.w << DIMLOG) | (unsigned)c.w };
#pragma unroll
    for (int j = 0; j < 4; j++) {
        unsigned w = f[j] >> 5, m = 1u << (f[j] & 31u);
        unsigned old = atomicOr(&g_bits[w].x, m);
        if (old & m) atomicOr(&g_bits[w].y, m);
    }
}

// S: single-pass scan (decoupled lookback) + full-line meta writes +
//    smem-staged compact of unique indices + dup-row zeroing + n_unique.
__global__ void k_scan_compact(float* __restrict__ out) {
    __shared__ unsigned sh_lbid, sh_prefix;
    __shared__ float s0[STAGE_CAP];
    __shared__ float s1[STAGE_CAP];
    unsigned tid = threadIdx.x;
    if (tid == 0) sh_lbid = atomicAdd(&g_ticket, 1u);
    __syncthreads();
    unsigned lbid = sh_lbid;
    unsigned base = lbid * (256u * SCAN_WPT) + tid * SCAN_WPT;

    uint2 bd[SCAN_WPT];
    unsigned s = 0;
#pragma unroll
    for (int j = 0; j < SCAN_WPT; j++) { bd[j] = g_bits[base + j]; s += __popc(bd[j].x); }
    unsigned tot;
    unsigned ex = block_exscan(s, tot);

    if (tid < 32) {
        if (tid == 0) atomicExch(&g_desc[lbid], (tot << 2) | (lbid == 0 ? 2u : 1u));
        unsigned prefix = 0;
        if (lbid > 0) {
            int look = (int)lbid - 1;
            unsigned running = 0;
            while (true) {
                int j = look - 31 + (int)tid;
                unsigned d;
                if (j < 0) d = 2u;
                else {
                    do { d = *((volatile unsigned*)(g_desc + j)); } while ((d & 3u) == 0u);
                }
                unsigned ball = __ballot_sync(0xffffffffu, (d & 3u) == 2u);
                if (ball) {
                    int hi = 31 - __clz(ball);
                    unsigned contrib = ((int)tid >= hi) ? (d >> 2) : 0u;
                    running += __reduce_add_sync(0xffffffffu, contrib);
                    break;
                } else {
                    running += __reduce_add_sync(0xffffffffu, d >> 2);
                    look -= 32;
                }
            }
            prefix = running;
            if (tid == 0) atomicExch(&g_desc[lbid], ((prefix + tot) << 2) | 2u);
        }
        if (tid == 0) sh_prefix = prefix;
    }
    __syncthreads();

    unsigned prefix = sh_prefix;
    unsigned off = prefix + ex;
    if (lbid == SCAN_BLOCKS - 1 && tid == 0) {
        unsigned nu = prefix + tot;
        g_total = nu;
        out[(size_t)2 * NNZ + (size_t)NNZ * DENSE] = (float)nu;
    }

    float* out0 = out;
    float* out1 = out + NNZ;
    float* vout = out + (size_t)2 * NNZ;
    bool staged = (tot <= STAGE_CAP);

#pragma unroll
    for (int j = 0; j < SCAN_WPT; j++) {
        unsigned w = base + j;
        unsigned bm = bd[j].x, dup = bd[j].y;
        uint4 m4; m4.x = bm; m4.y = dup; m4.z = off; m4.w = 0u;
        g_meta[w] = m4;                          // full-line STG.128
        unsigned o = off;
        unsigned v = bm;
        while (v) {
            unsigned b = (unsigned)__ffs(v) - 1u;
            v &= v - 1u;
            unsigned cell = (w << 5) | b;
            float rf = (float)(cell >> DIMLOG);
            float cf = (float)(cell & (DIMSZ - 1));
            if (staged) {
                unsigned lo = o - prefix;
                s0[lo] = rf; s1[lo] = cf;
            } else {
                __stcs(out0 + o, rf);
                __stcs(out1 + o, cf);
            }
            if ((dup >> b) & 1u) {
                float4* p = (float4*)(vout + (size_t)o * DENSE);
                float4 z = {0.f, 0.f, 0.f, 0.f};
                __stcs(p + 0, z); __stcs(p + 1, z); __stcs(p + 2, z); __stcs(p + 3, z);
            }
            o++;
        }
        off = o;
    }

    if (staged) {
        __syncthreads();
        for (unsigned i = tid; i < tot; i += 256u) {
            __stcs(out0 + prefix + i, s0[i]);
            __stcs(out1 + prefix + i, s1[i]);
        }
    }
}

// E: scatter values. 16 rows/warp; lanes 0..15 resolve (slot,dup) per row,
// every lane then moves 32B (two independent float4s). Non-dup row stores use
// DEFAULT write-back policy (not .cs): each 64B row is half a 128B L2 line,
// and with 126MB L2 vs a 260MB region, neighbor rows written by other warps
// pair up in L2 before eviction -> full-line DRAM write bursts.
// Fused tail fill in extra blocks.
__global__ void k_scatter(const int* __restrict__ idx,
                          const float* __restrict__ vals,
                          float* __restrict__ out) {
    if (blockIdx.x >= MAIN_BLOCKS) {
        unsigned nu = g_total;
        unsigned t0 = (blockIdx.x - MAIN_BLOCKS) * 256u + threadIdx.x;
        float4 z = {0.f, 0.f, 0.f, 0.f};
        for (unsigned slot = nu + t0; slot < NNZ; slot += TAIL_BLOCKS * 256u) {
            __stcs(out + slot, 8192.0f);
            __stcs(out + NNZ + slot, 0.0f);
            float4* v = (float4*)(out + (size_t)2 * NNZ + (size_t)slot * DENSE);
            __stcs(v + 0, z); __stcs(v + 1, z); __stcs(v + 2, z); __stcs(v + 3, z);
        }
        return;
    }

    unsigned t = blockIdx.x * 256u + threadIdx.x;
    unsigned lane = threadIdx.x & 31u;
    unsigned warpRow0 = (t >> 5) * 16u;

    unsigned packed = 0;
    if (lane < 16) {
        unsigned r = warpRow0 + lane;
        unsigned flat = ((unsigned)__ldg(idx + r) << DIMLOG) | (unsigned)__ldg(idx + NNZ + r);
        unsigned w = flat >> 5, b = flat & 31u;
        uint4 mt = __ldg(&g_meta[w]);
        unsigned slot = mt.z + __popc(mt.x & ((1u << b) - 1u));
        packed = (slot << 1) | ((mt.y >> b) & 1u);
    }
    packed = __shfl_sync(0xffffffffu, packed, lane >> 1);
    unsigned slot = packed >> 1, dup = packed & 1u;
    unsigned sub = (lane & 1u) * 2u;
    unsigned i = warpRow0 + (lane >> 1);

    const float4* src = (const float4*)vals + (size_t)i * 4 + sub;
    float4 v0 = __ldcs(src + 0);
    float4 v1 = __ldcs(src + 1);
    float* dst = out + (size_t)2 * NNZ + (size_t)slot * DENSE + sub * 4;
    if (dup) {
        atomicAdd(dst + 0, v0.x); atomicAdd(dst + 1, v0.y);
        atomicAdd(dst + 2, v0.z); atomicAdd(dst + 3, v0.w);
        atomicAdd(dst + 4, v1.x); atomicAdd(dst + 5, v1.y);
        atomicAdd(dst + 6, v1.z); atomicAdd(dst + 7, v1.w);
    } else {
        ((float4*)dst)[0] = v0;      // default write-back: L2 line pairing
        ((float4*)dst)[1] = v1;
    }
}

// ---------------------------------------------------------------------------
extern "C" void kernel_launch(void* const* d_in, const int* in_sizes, int n_in,
                              void* d_out, int out_size) {
    (void)in_sizes; (void)n_in; (void)out_size;
    const int*   idx  = (const int*)d_in[0];
    const float* vals = (const float*)d_in[1];
    float* out = (float*)d_out;

    unsigned zcnt = WORDS / 2 + SCAN_BLOCKS / 4 + 1;
    k_zero        <<<(zcnt + 255) / 256, 256>>>();
    k_mark        <<<NNZ / 4 / 256,      256>>>(idx);
    k_scan_compact<<<SCAN_BLOCKS,        256>>>(out);
    k_scatter     <<<MAIN_BLOCKS + TAIL_BLOCKS, 256>>>(idx, vals, out);
}